// round 3
// baseline (speedup 1.0000x reference)
#include <cuda_runtime.h>
#include <cuda_bf16.h>

#define BATCH   4096
#define HN      16
#define N1      192
#define DIM     256
#define TWO_DIM 512
#define EPS     1e-5f

// One CTA per batch b: handles all 16 heads (they share global_index_s[b]).
// Phases: scatter -> LayerNorm -> GEMM1(+ReLU) -> GEMM2 (only gathered cols) + sigmoid -> store.
__global__ __launch_bounds__(256, 3)
void mlp_two_fused(const float* __restrict__ rgb,
                   const float* __restrict__ tir,
                   const int*   __restrict__ gidx,
                   const float* __restrict__ ln_g,
                   const float* __restrict__ ln_b,
                   const float* __restrict__ W1,
                   const float* __restrict__ b1,
                   const float* __restrict__ W2,
                   const float* __restrict__ b2,
                   float* __restrict__ out)
{
    __shared__ float xs[HN][TWO_DIM];   // 32 KB  normalized input rows
    __shared__ float hs[HN][DIM];       // 16 KB  hidden activations

    const int b   = blockIdx.x;
    const int tid = threadIdx.x;

    // ---- zero xs ----
    float4* xs4z = reinterpret_cast<float4*>(&xs[0][0]);
    #pragma unroll
    for (int i = 0; i < (HN * TWO_DIM / 4) / 256; i++)
        xs4z[tid + i * 256] = make_float4(0.f, 0.f, 0.f, 0.f);
    __syncthreads();

    // ---- scatter rgb/tir into vex ----
    const int*   idxb = gidx + b * N1;
    const float* rgbb = rgb + (size_t)b * HN * N1;
    const float* tirb = tir + (size_t)b * HN * N1;
    for (int i = tid; i < HN * N1; i += 256) {
        int h = i / N1;
        int j = i - h * N1;
        int c = idxb[j];
        xs[h][c]       = rgbb[i];
        xs[h][DIM + c] = tirb[i];
    }
    __syncthreads();

    // ---- LayerNorm over 512, warp w handles rows 2w and 2w+1 ----
    const int wid = tid >> 5, lane = tid & 31;
    #pragma unroll
    for (int rr = 0; rr < 2; rr++) {
        const int r = wid * 2 + rr;
        float s = 0.f, sq = 0.f;
        #pragma unroll
        for (int k = lane; k < TWO_DIM; k += 32) {
            float v = xs[r][k];
            s += v; sq += v * v;
        }
        #pragma unroll
        for (int o = 16; o > 0; o >>= 1) {
            s  += __shfl_xor_sync(0xffffffffu, s,  o);
            sq += __shfl_xor_sync(0xffffffffu, sq, o);
        }
        const float mu  = s * (1.0f / TWO_DIM);
        const float var = sq * (1.0f / TWO_DIM) - mu * mu;
        const float rs  = rsqrtf(var + EPS);
        #pragma unroll
        for (int k = lane; k < TWO_DIM; k += 32) {
            float v = xs[r][k];
            xs[r][k] = (v - mu) * rs * __ldg(&ln_g[k]) + __ldg(&ln_b[k]);
        }
    }
    __syncthreads();

    // ---- GEMM1: hs[r][d] = relu( sum_e xs[r][e] * W1[d][e] + b1[d] ), d = tid ----
    {
        const int d = tid;
        float acc[HN];
        const float bb = __ldg(&b1[d]);
        #pragma unroll
        for (int r = 0; r < HN; r++) acc[r] = bb;

        const float4* w4 = reinterpret_cast<const float4*>(W1 + (size_t)d * TWO_DIM);
        #pragma unroll 2
        for (int k4 = 0; k4 < TWO_DIM / 4; k4++) {
            const float4 w = w4[k4];
            #pragma unroll
            for (int r = 0; r < HN; r++) {
                const float4 x = reinterpret_cast<const float4*>(&xs[r][0])[k4];
                acc[r] = fmaf(x.x, w.x, fmaf(x.y, w.y, fmaf(x.z, w.z, fmaf(x.w, w.w, acc[r]))));
            }
        }
        #pragma unroll
        for (int r = 0; r < HN; r++) hs[r][d] = fmaxf(acc[r], 0.0f);
    }
    __syncthreads();

    // ---- GEMM2 on gathered columns only: thread t<192 computes cols idx[t] and DIM+idx[t] ----
    if (tid < N1) {
        const int c = idxb[tid];
        float acc0[HN], acc1[HN];
        const float bb0 = __ldg(&b2[c]);
        const float bb1 = __ldg(&b2[DIM + c]);
        #pragma unroll
        for (int r = 0; r < HN; r++) { acc0[r] = bb0; acc1[r] = bb1; }

        const float4* w0 = reinterpret_cast<const float4*>(W2 + (size_t)c * DIM);
        const float4* w1 = reinterpret_cast<const float4*>(W2 + (size_t)(DIM + c) * DIM);
        #pragma unroll 2
        for (int k4 = 0; k4 < DIM / 4; k4++) {
            const float4 a0 = w0[k4];
            const float4 a1 = w1[k4];
            #pragma unroll
            for (int r = 0; r < HN; r++) {
                const float4 h = reinterpret_cast<const float4*>(&hs[r][0])[k4];
                acc0[r] = fmaf(h.x, a0.x, fmaf(h.y, a0.y, fmaf(h.z, a0.z, fmaf(h.w, a0.w, acc0[r]))));
                acc1[r] = fmaf(h.x, a1.x, fmaf(h.y, a1.y, fmaf(h.z, a1.z, fmaf(h.w, a1.w, acc1[r]))));
            }
        }

        const size_t base     = (size_t)b * HN * N1;
        const size_t tir_off  = (size_t)BATCH * HN * N1;
        #pragma unroll
        for (int r = 0; r < HN; r++) {
            const float o0 = 1.0f / (1.0f + __expf(-acc0[r]));
            const float o1 = 1.0f / (1.0f + __expf(-acc1[r]));
            out[base + (size_t)r * N1 + tid]           = o0;
            out[tir_off + base + (size_t)r * N1 + tid] = o1;
        }
    }
}

extern "C" void kernel_launch(void* const* d_in, const int* in_sizes, int n_in,
                              void* d_out, int out_size) {
    const float* rgb  = (const float*)d_in[0];
    const float* tir  = (const float*)d_in[1];
    const int*   gidx = (const int*)  d_in[2];
    const float* ln_g = (const float*)d_in[3];
    const float* ln_b = (const float*)d_in[4];
    const float* W1   = (const float*)d_in[5];
    const float* b1   = (const float*)d_in[6];
    const float* W2   = (const float*)d_in[7];
    const float* b2   = (const float*)d_in[8];

    mlp_two_fused<<<BATCH, 256>>>(rgb, tir, gidx, ln_g, ln_b, W1, b1, W2, b2,
                                  (float*)d_out);
}

// round 4
// speedup vs baseline: 1.0166x; 1.0166x over previous
#include <cuda_runtime.h>
#include <cuda_bf16.h>

#define BATCH   4096
#define HN      16
#define N1      192
#define DIM     256
#define TWO_DIM 512
#define EPS     1e-5f

#define XS_STRIDE 20          // 16 r + pad, keeps 16B alignment for r-quads
#define HS_STRIDE 20
#define WT1_STRIDE 258        // 256 d + pad2
#define WT2_STRIDE 514        // 512 d + pad2
#define KT1 32                // k-tile GEMM1 (16 tiles over K=512)
#define KT2 16                // k-tile GEMM2 (16 tiles over K=256)

// smem word offsets
#define OFF_XST  0                         // 512*20 = 10240 words (osT aliases this)
#define OFF_HST  10240                     // 256*20 = 5120
#define OFF_WT   15360                     // 32*258 = 8256 (also holds 16*514 = 8224)
#define OFF_IDX  23616                     // 192 ints
#define SMEM_WORDS 23808                   // 95232 bytes

typedef unsigned long long ull;

__device__ __forceinline__ ull splat2(float w) {
    ull r;
    asm("mov.b64 %0, {%1, %1};" : "=l"(r) : "f"(w));
    return r;
}
__device__ __forceinline__ void fma2(ull& acc, ull a, ull b) {
    asm("fma.rn.f32x2 %0, %1, %2, %0;" : "+l"(acc) : "l"(a), "l"(b));
}
__device__ __forceinline__ void unpack2(ull v, float& lo, float& hi) {
    asm("mov.b64 {%0, %1}, %2;" : "=f"(lo), "=f"(hi) : "l"(v));
}

__global__ __launch_bounds__(256, 2)
void mlp_two_fused(const float* __restrict__ rgb,
                   const float* __restrict__ tir,
                   const int*   __restrict__ gidx,
                   const float* __restrict__ ln_g,
                   const float* __restrict__ ln_b,
                   const float* __restrict__ W1,
                   const float* __restrict__ b1,
                   const float* __restrict__ W2,
                   const float* __restrict__ b2,
                   float* __restrict__ out)
{
    extern __shared__ float smem[];
    float* xsT   = smem + OFF_XST;   // [512][XS_STRIDE], element (k,r) at k*20+r
    float* hsT   = smem + OFF_HST;   // [256][HS_STRIDE]
    float* wt    = smem + OFF_WT;    // W tile, [k][d] padded
    int*   idx_s = (int*)(smem + OFF_IDX);
    float* osT   = xsT;              // [512][16] alias, used after GEMM1

    const int b   = blockIdx.x;
    const int tid = threadIdx.x;

    // ---- load idx, zero xsT ----
    if (tid < N1) idx_s[tid] = gidx[b * N1 + tid];
    {
        float4* z = reinterpret_cast<float4*>(xsT);
        #pragma unroll
        for (int i = 0; i < (TWO_DIM * XS_STRIDE / 4) / 256; i++)
            z[tid + i * 256] = make_float4(0.f, 0.f, 0.f, 0.f);
    }
    __syncthreads();

    // ---- scatter into transposed xsT[c][h] ----
    const float* rgbb = rgb + (size_t)b * HN * N1;
    const float* tirb = tir + (size_t)b * HN * N1;
    #pragma unroll
    for (int i = tid; i < HN * N1; i += 256) {
        int h = i / N1;
        int j = i - h * N1;
        int c = idx_s[j];
        xsT[c * XS_STRIDE + h]         = rgbb[i];
        xsT[(DIM + c) * XS_STRIDE + h] = tirb[i];
    }
    __syncthreads();

    // ---- LayerNorm: warp w handles rows 2w, 2w+1 (columns of xsT) ----
    const int wid = tid >> 5, lane = tid & 31;
    #pragma unroll
    for (int rr = 0; rr < 2; rr++) {
        const int r = wid * 2 + rr;
        float s = 0.f, sq = 0.f;
        #pragma unroll
        for (int k = lane; k < TWO_DIM; k += 32) {
            float v = xsT[k * XS_STRIDE + r];
            s += v; sq += v * v;
        }
        #pragma unroll
        for (int o = 16; o > 0; o >>= 1) {
            s  += __shfl_xor_sync(0xffffffffu, s,  o);
            sq += __shfl_xor_sync(0xffffffffu, sq, o);
        }
        const float mu  = s * (1.0f / TWO_DIM);
        const float var = sq * (1.0f / TWO_DIM) - mu * mu;
        const float rs  = rsqrtf(var + EPS);
        #pragma unroll
        for (int k = lane; k < TWO_DIM; k += 32) {
            float v = xsT[k * XS_STRIDE + r];
            xsT[k * XS_STRIDE + r] = (v - mu) * rs * __ldg(&ln_g[k]) + __ldg(&ln_b[k]);
        }
    }

    // ============ GEMM1: h[r][d] = relu(x[r][:] . W1[d][:] + b1[d]) ============
    // thread owns column d = tid; accumulators are r-pairs in f32x2
    {
        const int d = tid;
        ull acc[8];
        {
            const ull bb2 = splat2(__ldg(&b1[d]));
            #pragma unroll
            for (int p = 0; p < 8; p++) acc[p] = bb2;
        }

        for (int t = 0; t < TWO_DIM / KT1; t++) {
            __syncthreads();   // protect wt from previous iteration's readers
            // stage W1 tile: wt[k][d] = W1[d][t*32 + k], coalesced float4 loads
            #pragma unroll
            for (int i = 0; i < 8; i++) {
                int q  = i * 256 + tid;       // 2048 float4 per tile
                int dq = q >> 3;              // 8 float4 per d-row
                int j  = q & 7;
                float4 v = __ldg(reinterpret_cast<const float4*>(
                               W1 + (size_t)dq * TWO_DIM + t * KT1 + 4 * j));
                wt[(4 * j + 0) * WT1_STRIDE + dq] = v.x;
                wt[(4 * j + 1) * WT1_STRIDE + dq] = v.y;
                wt[(4 * j + 2) * WT1_STRIDE + dq] = v.z;
                wt[(4 * j + 3) * WT1_STRIDE + dq] = v.w;
            }
            __syncthreads();

            #pragma unroll
            for (int k = 0; k < KT1; k++) {
                const ull w2 = splat2(wt[k * WT1_STRIDE + d]);
                const ulonglong2* xp = reinterpret_cast<const ulonglong2*>(
                    xsT + (t * KT1 + k) * XS_STRIDE);
                ulonglong2 x01 = xp[0];   // r0..r3
                ulonglong2 x23 = xp[1];   // r4..r7
                ulonglong2 x45 = xp[2];   // r8..r11
                ulonglong2 x67 = xp[3];   // r12..r15
                fma2(acc[0], x01.x, w2); fma2(acc[1], x01.y, w2);
                fma2(acc[2], x23.x, w2); fma2(acc[3], x23.y, w2);
                fma2(acc[4], x45.x, w2); fma2(acc[5], x45.y, w2);
                fma2(acc[6], x67.x, w2); fma2(acc[7], x67.y, w2);
            }
        }

        // ReLU + write transposed hidden hsT[d][r]
        #pragma unroll
        for (int p = 0; p < 8; p++) {
            float f0, f1;
            unpack2(acc[p], f0, f1);
            float2 v = make_float2(fmaxf(f0, 0.f), fmaxf(f1, 0.f));
            *reinterpret_cast<float2*>(hsT + d * HS_STRIDE + 2 * p) = v;
        }
    }
    __syncthreads();

    // ============ GEMM2: o[r][d] = sigmoid(h[r][:] . W2[d][:] + b2[d]), d in [0,512) ====
    // thread owns columns d0 = 2*tid, d1 = 2*tid+1
    {
        const int d0 = 2 * tid, d1 = 2 * tid + 1;
        ull acc0[8], acc1[8];
        {
            const ull bb0 = splat2(__ldg(&b2[d0]));
            const ull bb1 = splat2(__ldg(&b2[d1]));
            #pragma unroll
            for (int p = 0; p < 8; p++) { acc0[p] = bb0; acc1[p] = bb1; }
        }

        for (int t = 0; t < DIM / KT2; t++) {
            __syncthreads();
            // stage W2 tile: wt[k][d] = W2[d][t*16 + k]
            #pragma unroll
            for (int i = 0; i < 8; i++) {
                int q  = i * 256 + tid;       // 2048 float4 per tile
                int dq = q >> 2;              // 4 float4 per d-row
                int j  = q & 3;
                float4 v = __ldg(reinterpret_cast<const float4*>(
                               W2 + (size_t)dq * DIM + t * KT2 + 4 * j));
                wt[(4 * j + 0) * WT2_STRIDE + dq] = v.x;
                wt[(4 * j + 1) * WT2_STRIDE + dq] = v.y;
                wt[(4 * j + 2) * WT2_STRIDE + dq] = v.z;
                wt[(4 * j + 3) * WT2_STRIDE + dq] = v.w;
            }
            __syncthreads();

            #pragma unroll
            for (int k = 0; k < KT2; k++) {
                ull wp = *reinterpret_cast<const ull*>(wt + k * WT2_STRIDE + d0);
                float wa, wb;
                unpack2(wp, wa, wb);
                const ull wa2 = splat2(wa);
                const ull wb2 = splat2(wb);
                const ulonglong2* hp = reinterpret_cast<const ulonglong2*>(
                    hsT + (t * KT2 + k) * HS_STRIDE);
                ulonglong2 h01 = hp[0];
                ulonglong2 h23 = hp[1];
                ulonglong2 h45 = hp[2];
                ulonglong2 h67 = hp[3];
                fma2(acc0[0], h01.x, wa2); fma2(acc1[0], h01.x, wb2);
                fma2(acc0[1], h01.y, wa2); fma2(acc1[1], h01.y, wb2);
                fma2(acc0[2], h23.x, wa2); fma2(acc1[2], h23.x, wb2);
                fma2(acc0[3], h23.y, wa2); fma2(acc1[3], h23.y, wb2);
                fma2(acc0[4], h45.x, wa2); fma2(acc1[4], h45.x, wb2);
                fma2(acc0[5], h45.y, wa2); fma2(acc1[5], h45.y, wb2);
                fma2(acc0[6], h67.x, wa2); fma2(acc1[6], h67.x, wb2);
                fma2(acc0[7], h67.y, wa2); fma2(acc1[7], h67.y, wb2);
            }
        }
        __syncthreads();   // xsT (aliased by osT) fully consumed before overwrite

        // sigmoid + store osT[d][r]
        #pragma unroll
        for (int p = 0; p < 8; p++) {
            float f0, f1, g0, g1;
            unpack2(acc0[p], f0, f1);
            unpack2(acc1[p], g0, g1);
            float2 v0 = make_float2(1.0f / (1.0f + __expf(-f0)),
                                    1.0f / (1.0f + __expf(-f1)));
            float2 v1 = make_float2(1.0f / (1.0f + __expf(-g0)),
                                    1.0f / (1.0f + __expf(-g1)));
            *reinterpret_cast<float2*>(osT + d0 * 16 + 2 * p) = v0;
            *reinterpret_cast<float2*>(osT + d1 * 16 + 2 * p) = v1;
        }
    }
    __syncthreads();

    // ---- gather outputs: out_rgb[b][r][j] = o[r][idx[j]], out_tir from DIM+idx ----
    {
        const size_t base    = (size_t)b * HN * N1;
        const size_t tir_off = (size_t)BATCH * HN * N1;
        #pragma unroll
        for (int e = tid; e < HN * N1; e += 256) {
            int r = e / N1;
            int j = e - r * N1;
            int c = idx_s[j];
            out[base + e]           = osT[c * 16 + r];
            out[tir_off + base + e] = osT[(DIM + c) * 16 + r];
        }
    }
}

extern "C" void kernel_launch(void* const* d_in, const int* in_sizes, int n_in,
                              void* d_out, int out_size) {
    const float* rgb  = (const float*)d_in[0];
    const float* tir  = (const float*)d_in[1];
    const int*   gidx = (const int*)  d_in[2];
    const float* ln_g = (const float*)d_in[3];
    const float* ln_b = (const float*)d_in[4];
    const float* W1   = (const float*)d_in[5];
    const float* b1   = (const float*)d_in[6];
    const float* W2   = (const float*)d_in[7];
    const float* b2   = (const float*)d_in[8];

    const int smem_bytes = SMEM_WORDS * 4;   // 95232
    cudaFuncSetAttribute(mlp_two_fused,
                         cudaFuncAttributeMaxDynamicSharedMemorySize, smem_bytes);
    mlp_two_fused<<<BATCH, 256, smem_bytes>>>(rgb, tir, gidx, ln_g, ln_b,
                                              W1, b1, W2, b2, (float*)d_out);
}

// round 6
// speedup vs baseline: 4.0395x; 3.9737x over previous
#include <cuda_runtime.h>
#include <cuda_bf16.h>
#include <cstdint>

#define BATCH   4096
#define HN      16
#define N1      192
#define DIM     256
#define TWO_DIM 512
#define EPS     1e-5f
#define GB      4            // batches per CTA
#define THREADS 512

// ---- smem layout (bytes) ----
#define OFF_R1   0           // 67584: x32 scatter half (65536) -> later hhi(33792)+hlo(33792)
#define OFF_HLO  33792
#define OFF_XHI  67584       // 66560: xhi -> later o (64 x 260 f32)
#define OFF_XLO  134144      // 66560
#define OFF_IDX  200704      // 768 ints
#define OFF_B1   203776      // 256 f32
#define OFF_B2   204800      // 512 f32
#define OFF_LNG  206848      // 512 f32
#define OFF_LNB  208896      // 512 f32
#define SMEM_BYTES 210944

#define XSTRIDE_W 260        // u32 words per xhi/xlo row (256 data + 4 pad; ≡4 mod 32)
#define XSTRIDE_B 1040
#define HSTRIDE_W 132        // u32 words per h row (128 data + 4 pad)
#define HSTRIDE_B 528
#define OSTRIDE_W 260        // f32 words per o row (256 data + 4 pad)

// Pre-swizzled weights in B-fragment order, hi/lo split. 512KB each.
__device__ __align__(16) __nv_bfloat16 g_W1s[262144];
__device__ __align__(16) __nv_bfloat16 g_W2s[262144];

__device__ __forceinline__ uint32_t smem_u32(const void* p) {
    return (uint32_t)__cvta_generic_to_shared(p);
}

__device__ __forceinline__ void ldsm4(uint32_t (&r)[4], uint32_t addr) {
    asm volatile("ldmatrix.sync.aligned.m8n8.x4.shared.b16 {%0,%1,%2,%3}, [%4];"
                 : "=r"(r[0]), "=r"(r[1]), "=r"(r[2]), "=r"(r[3]) : "r"(addr));
}

__device__ __forceinline__ void mma16816(float (&c)[4], const uint32_t (&a)[4],
                                         uint32_t b0, uint32_t b1) {
    asm volatile("mma.sync.aligned.m16n8k16.row.col.f32.bf16.bf16.f32 "
                 "{%0,%1,%2,%3}, {%4,%5,%6,%7}, {%8,%9}, {%0,%1,%2,%3};"
                 : "+f"(c[0]), "+f"(c[1]), "+f"(c[2]), "+f"(c[3])
                 : "r"(a[0]), "r"(a[1]), "r"(a[2]), "r"(a[3]), "r"(b0), "r"(b1));
}

__device__ __forceinline__ float sigmoidf(float x) {
    return 1.0f / (1.0f + __expf(-x));
}

// Swizzle W[n][k] (row-major [Nout][K]) into per-tile B-fragment chunks:
// u32 index t = (((ntile*kpairs + kp)*2 + ver)*32 + lane)*4 + j
// lane holds, per 2-ktile chunk, regs j=0..3: (b0,b1 of ktile0, b0,b1 of ktile1)
__global__ void prep_weights(const float* __restrict__ W, int which,
                             int ntiles, int kpairs, int K) {
    int t = blockIdx.x * blockDim.x + threadIdx.x;
    int total = ntiles * kpairs * 256;
    if (t >= total) return;
    int j    = t & 3;
    int lane = (t >> 2) & 31;
    int cv   = t >> 7;
    int ver  = cv & 1;
    int rest = cv >> 1;
    int kp    = rest % kpairs;
    int ntile = rest / kpairs;
    int n = ntile * 8 + (lane >> 2);
    int k = kp * 32 + (j >> 1) * 16 + (j & 1) * 8 + 2 * (lane & 3);
    float w0 = W[n * K + k];
    float w1 = W[n * K + k + 1];
    __nv_bfloat16 h0 = __float2bfloat16(w0);
    __nv_bfloat16 h1 = __float2bfloat16(w1);
    __nv_bfloat162 pr;
    if (ver == 0) { pr.x = h0; pr.y = h1; }
    else {
        pr.x = __float2bfloat16(w0 - __bfloat162float(h0));
        pr.y = __float2bfloat16(w1 - __bfloat162float(h1));
    }
    __nv_bfloat162* dst = (__nv_bfloat162*)(which ? g_W2s : g_W1s);
    dst[t] = pr;
}

__global__ __launch_bounds__(THREADS, 1)
void mlp_two_main(const float* __restrict__ rgb, const float* __restrict__ tir,
                  const int* __restrict__ gidx, const float* __restrict__ ln_g,
                  const float* __restrict__ ln_b, const float* __restrict__ b1,
                  const float* __restrict__ b2, float* __restrict__ out)
{
    extern __shared__ char smem[];
    float*    x32  = (float*)(smem + OFF_R1);
    uint32_t* hhi  = (uint32_t*)(smem + OFF_R1);
    uint32_t* hlo  = (uint32_t*)(smem + OFF_HLO);
    uint32_t* xhi  = (uint32_t*)(smem + OFF_XHI);
    uint32_t* xlo  = (uint32_t*)(smem + OFF_XLO);
    float*    osm  = (float*)(smem + OFF_XHI);
    int*      idx_s = (int*)(smem + OFF_IDX);
    float*    b1s  = (float*)(smem + OFF_B1);
    float*    b2s  = (float*)(smem + OFF_B2);
    float*    lngs = (float*)(smem + OFF_LNG);
    float*    lnbs = (float*)(smem + OFF_LNB);

    const int tid  = threadIdx.x;
    const int lane = tid & 31;
    const int wid  = tid >> 5;

    // ---- preload idx / biases / LN params ----
    if (tid < 256) b1s[tid] = b1[tid];
    b2s[tid]  = b2[tid];
    lngs[tid] = ln_g[tid];
    lnbs[tid] = ln_b[tid];
    {
        int e = tid;
        idx_s[e] = gidx[blockIdx.x * (GB * N1) + e];
        e += THREADS;
        if (e < GB * N1) idx_s[e] = gidx[blockIdx.x * (GB * N1) + e];
    }

    const float* rgb_cta = rgb + (size_t)blockIdx.x * (GB * HN * N1);
    const float* tir_cta = tir + (size_t)blockIdx.x * (GB * HN * N1);

    // ======== scatter + LayerNorm + bf16 hi/lo split, in two 32-row passes ========
    for (int p = 0; p < 2; p++) {
        __syncthreads();
        float4* z = (float4*)x32;
        #pragma unroll
        for (int i = 0; i < (32 * 512 / 4) / THREADS; i++)
            z[tid + i * THREADS] = make_float4(0.f, 0.f, 0.f, 0.f);
        __syncthreads();

        const int ebase = p * (2 * HN * N1);
        #pragma unroll
        for (int ii = 0; ii < (2 * HN * N1) / THREADS; ii++) {
            int e   = ii * THREADS + tid;
            int row = e / N1;                  // 0..31
            int j   = e - row * N1;
            int g   = row >> 4;                // local batch 0/1
            int c   = idx_s[(2 * p + g) * N1 + j];
            x32[row * 512 + c]        = rgb_cta[ebase + e];
            x32[row * 512 + DIM + c]  = tir_cta[ebase + e];
        }
        __syncthreads();

        #pragma unroll
        for (int rr = 0; rr < 2; rr++) {
            int rl = wid * 2 + rr;             // 0..31
            int rg = p * 32 + rl;              // global row
            const float* xr = x32 + rl * 512;
            float s = 0.f, sq = 0.f;
            #pragma unroll
            for (int k = lane; k < 512; k += 32) {
                float v = xr[k]; s += v; sq += v * v;
            }
            #pragma unroll
            for (int o = 16; o > 0; o >>= 1) {
                s  += __shfl_xor_sync(~0u, s,  o);
                sq += __shfl_xor_sync(~0u, sq, o);
            }
            float mu = s * (1.f / 512.f);
            float rs = rsqrtf(sq * (1.f / 512.f) - mu * mu + EPS);
            #pragma unroll
            for (int k2 = lane; k2 < 256; k2 += 32) {
                float2 v  = *(const float2*)(xr + 2 * k2);
                float2 g2 = *(const float2*)(lngs + 2 * k2);
                float2 bb = *(const float2*)(lnbs + 2 * k2);
                float v0 = (v.x - mu) * rs * g2.x + bb.x;
                float v1 = (v.y - mu) * rs * g2.y + bb.y;
                __nv_bfloat162 hi = __float22bfloat162_rn(make_float2(v0, v1));
                __nv_bfloat162 lo = __float22bfloat162_rn(
                    make_float2(v0 - __bfloat162float(hi.x),
                                v1 - __bfloat162float(hi.y)));
                xhi[rg * XSTRIDE_W + k2] = *(uint32_t*)&hi;
                xlo[rg * XSTRIDE_W + k2] = *(uint32_t*)&lo;
            }
        }
    }
    __syncthreads();

    // ---- warp tile geometry (shared by both GEMMs) ----
    const int mtile  = wid & 3, ngroup = wid >> 2;
    const int m0     = mtile * 16;
    const int q      = lane >> 3, qr = lane & 7;
    const int arow   = m0 + (q & 1) * 8 + qr;
    const uint32_t acol = (q >> 1) * 16;   // bytes
    const uint32_t xhi_a = smem_u32(smem + OFF_XHI) + arow * XSTRIDE_B + acol;
    const uint32_t xlo_a = smem_u32(smem + OFF_XLO) + arow * XSTRIDE_B + acol;

    // ======== GEMM1: [64x512] @ W1^T -> h [64x256], 3-pass bf16 split ========
    {
        float acc[8][4];
        #pragma unroll
        for (int nt = 0; nt < 8; nt++)
            { acc[nt][0]=0.f; acc[nt][1]=0.f; acc[nt][2]=0.f; acc[nt][3]=0.f; }

        #pragma unroll 2
        for (int kp = 0; kp < 16; kp++) {
            uint32_t ah0[4], ah1[4], al0[4], al1[4];
            ldsm4(ah0, xhi_a + kp * 64);
            ldsm4(ah1, xhi_a + kp * 64 + 32);
            ldsm4(al0, xlo_a + kp * 64);
            ldsm4(al1, xlo_a + kp * 64 + 32);
            #pragma unroll
            for (int nt = 0; nt < 8; nt++) {
                int ntile = ngroup * 8 + nt;
                const uint4* wp = ((const uint4*)g_W1s) + ((ntile * 16 + kp) * 2) * 32 + lane;
                uint4 bh = __ldg(wp);
                uint4 bl = __ldg(wp + 32);
                mma16816(acc[nt], ah0, bh.x, bh.y);
                mma16816(acc[nt], ah1, bh.z, bh.w);
                mma16816(acc[nt], ah0, bl.x, bl.y);
                mma16816(acc[nt], ah1, bl.z, bl.w);
                mma16816(acc[nt], al0, bh.x, bh.y);
                mma16816(acc[nt], al1, bh.z, bh.w);
            }
        }
        // epilogue: +bias, relu, split, store h (overwrites dead x32 region)
        int r0 = m0 + (lane >> 2), r1 = r0 + 8;
        int cwb = ngroup * 32 + (lane & 3);
        #pragma unroll
        for (int nt = 0; nt < 8; nt++) {
            int cw = cwb + nt * 4;
            float2 bb = *(const float2*)(b1s + 2 * cw);
            float v00 = fmaxf(acc[nt][0] + bb.x, 0.f);
            float v01 = fmaxf(acc[nt][1] + bb.y, 0.f);
            float v10 = fmaxf(acc[nt][2] + bb.x, 0.f);
            float v11 = fmaxf(acc[nt][3] + bb.y, 0.f);
            __nv_bfloat162 h0 = __float22bfloat162_rn(make_float2(v00, v01));
            __nv_bfloat162 l0 = __float22bfloat162_rn(
                make_float2(v00 - __bfloat162float(h0.x), v01 - __bfloat162float(h0.y)));
            __nv_bfloat162 h1 = __float22bfloat162_rn(make_float2(v10, v11));
            __nv_bfloat162 l1 = __float22bfloat162_rn(
                make_float2(v10 - __bfloat162float(h1.x), v11 - __bfloat162float(h1.y)));
            hhi[r0 * HSTRIDE_W + cw] = *(uint32_t*)&h0;
            hlo[r0 * HSTRIDE_W + cw] = *(uint32_t*)&l0;
            hhi[r1 * HSTRIDE_W + cw] = *(uint32_t*)&h1;
            hlo[r1 * HSTRIDE_W + cw] = *(uint32_t*)&l1;
        }
    }
    __syncthreads();

    // ======== GEMM2 (two 256-col halves) + sigmoid + gather ========
    const uint32_t hhi_a = smem_u32(smem + OFF_R1) + arow * HSTRIDE_B + acol;
    const uint32_t hlo_a = hhi_a + 33792;
    const size_t out_base = (size_t)blockIdx.x * (GB * HN * N1);
    const size_t TIR_OFF  = (size_t)BATCH * HN * N1;

    #pragma unroll 1
    for (int hf = 0; hf < 2; hf++) {
        float acc[8][4];
        #pragma unroll
        for (int nt = 0; nt < 8; nt++)
            { acc[nt][0]=0.f; acc[nt][1]=0.f; acc[nt][2]=0.f; acc[nt][3]=0.f; }

        #pragma unroll 2
        for (int kp = 0; kp < 8; kp++) {
            uint32_t ah0[4], ah1[4], al0[4], al1[4];
            ldsm4(ah0, hhi_a + kp * 64);
            ldsm4(ah1, hhi_a + kp * 64 + 32);
            ldsm4(al0, hlo_a + kp * 64);
            ldsm4(al1, hlo_a + kp * 64 + 32);
            #pragma unroll
            for (int nt = 0; nt < 8; nt++) {
                int ntile = hf * 32 + ngroup * 8 + nt;
                const uint4* wp = ((const uint4*)g_W2s) + ((ntile * 8 + kp) * 2) * 32 + lane;
                uint4 bh = __ldg(wp);
                uint4 bl = __ldg(wp + 32);
                mma16816(acc[nt], ah0, bh.x, bh.y);
                mma16816(acc[nt], ah1, bh.z, bh.w);
                mma16816(acc[nt], ah0, bl.x, bl.y);
                mma16816(acc[nt], ah1, bl.z, bl.w);
                mma16816(acc[nt], al0, bh.x, bh.y);
                mma16816(acc[nt], al1, bh.z, bh.w);
            }
        }
        // epilogue: +bias, sigmoid, store to o (overwrites dead xhi region)
        {
            int r0 = m0 + (lane >> 2), r1 = r0 + 8;
            int clb = ngroup * 64 + 2 * (lane & 3);
            #pragma unroll
            for (int nt = 0; nt < 8; nt++) {
                int c = clb + nt * 8;
                float2 bb = *(const float2*)(b2s + hf * 256 + c);
                float2 v0 = make_float2(sigmoidf(acc[nt][0] + bb.x),
                                        sigmoidf(acc[nt][1] + bb.y));
                float2 v1 = make_float2(sigmoidf(acc[nt][2] + bb.x),
                                        sigmoidf(acc[nt][3] + bb.y));
                *(float2*)(osm + r0 * OSTRIDE_W + c) = v0;
                *(float2*)(osm + r1 * OSTRIDE_W + c) = v1;
            }
        }
        __syncthreads();

        // gather this half's outputs
        const size_t obase = (hf ? TIR_OFF : 0) + out_base;
        #pragma unroll
        for (int ii = 0; ii < (GB * HN * N1) / THREADS; ii++) {
            int e   = ii * THREADS + tid;
            int row = e / N1;              // 0..63
            int j   = e - row * N1;
            int g   = row >> 4;
            int c   = idx_s[g * N1 + j];
            out[obase + e] = osm[row * OSTRIDE_W + c];
        }
        __syncthreads();
    }
}

extern "C" void kernel_launch(void* const* d_in, const int* in_sizes, int n_in,
                              void* d_out, int out_size) {
    const float* rgb  = (const float*)d_in[0];
    const float* tir  = (const float*)d_in[1];
    const int*   gidx = (const int*)  d_in[2];
    const float* ln_g = (const float*)d_in[3];
    const float* ln_b = (const float*)d_in[4];
    const float* W1   = (const float*)d_in[5];
    const float* b1   = (const float*)d_in[6];
    const float* W2   = (const float*)d_in[7];
    const float* b2   = (const float*)d_in[8];

    // pre-swizzle weights into fragment order (hi/lo split)
    prep_weights<<<512, 256>>>(W1, 0, 32, 16, 512);
    prep_weights<<<512, 256>>>(W2, 1, 64, 8, 256);

    cudaFuncSetAttribute(mlp_two_main,
                         cudaFuncAttributeMaxDynamicSharedMemorySize, SMEM_BYTES);
    mlp_two_main<<<BATCH / GB, THREADS, SMEM_BYTES>>>(
        rgb, tir, gidx, ln_g, ln_b, b1, b2, (float*)d_out);
}

// round 9
// speedup vs baseline: 5.1269x; 1.2692x over previous
#include <cuda_runtime.h>
#include <cuda_fp16.h>
#include <cstdint>

#define BATCH   4096
#define HN      16
#define N1      192
#define DIM     256
#define TWO_DIM 512
#define EPS     1e-5f
#define GB      4            // batches per CTA
#define THREADS 512

// ---- smem layout (bytes) ----
#define OFF_R1   0           // x32 scatter half (65536) -> later hhi(33792)+hlo(33792)
#define OFF_HLO  33792
#define OFF_XHI  67584       // 66560: xhi -> later o (64 x 260 f32)
#define OFF_XLO  134144      // 66560
#define OFF_IDX  200704      // 768 ints
#define OFF_B1   203776      // 256 f32
#define OFF_B2   204800      // 512 f32
#define OFF_LNG  206848      // 512 f32
#define OFF_LNB  208896      // 512 f32
#define SMEM_BYTES 210944

#define XSTRIDE_W 260        // u32 words per xhi/xlo row (256 data + 4 pad; ≡4 mod 32)
#define XSTRIDE_B 1040
#define HSTRIDE_W 132        // u32 words per h row (128 data + 4 pad)
#define HSTRIDE_B 528
#define OSTRIDE_W 260        // f32 words per o row (256 data + 4 pad)

// Pre-swizzled fp16 weights in B-fragment order (hi only). 256KB each.
__device__ __align__(16) __half g_W1s[131072];
__device__ __align__(16) __half g_W2s[131072];

__device__ __forceinline__ uint32_t smem_u32(const void* p) {
    return (uint32_t)__cvta_generic_to_shared(p);
}

__device__ __forceinline__ void ldsm4(uint32_t (&r)[4], uint32_t addr) {
    asm volatile("ldmatrix.sync.aligned.m8n8.x4.shared.b16 {%0,%1,%2,%3}, [%4];"
                 : "=r"(r[0]), "=r"(r[1]), "=r"(r[2]), "=r"(r[3]) : "r"(addr));
}

__device__ __forceinline__ void mma16816(float (&c)[4], const uint32_t (&a)[4],
                                         uint32_t b0, uint32_t b1) {
    asm volatile("mma.sync.aligned.m16n8k16.row.col.f32.f16.f16.f32 "
                 "{%0,%1,%2,%3}, {%4,%5,%6,%7}, {%8,%9}, {%0,%1,%2,%3};"
                 : "+f"(c[0]), "+f"(c[1]), "+f"(c[2]), "+f"(c[3])
                 : "r"(a[0]), "r"(a[1]), "r"(a[2]), "r"(a[3]), "r"(b0), "r"(b1));
}

__device__ __forceinline__ float sigmoidf(float x) {
    return 1.0f / (1.0f + __expf(-x));
}

// Swizzle W[n][k] (row-major [Nout][K]) into per-tile B-fragment chunks (fp16 hi):
// u32 index t = ((ntile*kpairs + kp)*32 + lane)*4 + j
__global__ void prep_weights(const float* __restrict__ W, int which,
                             int ntiles, int kpairs, int K) {
    int t = blockIdx.x * blockDim.x + threadIdx.x;
    int total = ntiles * kpairs * 128;
    if (t >= total) return;
    int j    = t & 3;
    int lane = (t >> 2) & 31;
    int rest = t >> 7;
    int kp    = rest % kpairs;
    int ntile = rest / kpairs;
    int n = ntile * 8 + (lane >> 2);
    int k = kp * 32 + (j >> 1) * 16 + (j & 1) * 8 + 2 * (lane & 3);
    __half2 pr = __floats2half2_rn(W[n * K + k], W[n * K + k + 1]);
    ((__half2*)(which ? g_W2s : g_W1s))[t] = pr;
}

__global__ __launch_bounds__(THREADS, 1)
void mlp_two_main(const float* __restrict__ rgb, const float* __restrict__ tir,
                  const int* __restrict__ gidx, const float* __restrict__ ln_g,
                  const float* __restrict__ ln_b, const float* __restrict__ b1,
                  const float* __restrict__ b2, float* __restrict__ out)
{
    extern __shared__ char smem[];
    float*    x32  = (float*)(smem + OFF_R1);
    uint32_t* hhi  = (uint32_t*)(smem + OFF_R1);
    uint32_t* hlo  = (uint32_t*)(smem + OFF_HLO);
    uint32_t* xhi  = (uint32_t*)(smem + OFF_XHI);
    uint32_t* xlo  = (uint32_t*)(smem + OFF_XLO);
    float*    osm  = (float*)(smem + OFF_XHI);
    int*      idx_s = (int*)(smem + OFF_IDX);
    float*    b1s  = (float*)(smem + OFF_B1);
    float*    b2s  = (float*)(smem + OFF_B2);
    float*    lngs = (float*)(smem + OFF_LNG);
    float*    lnbs = (float*)(smem + OFF_LNB);

    const int tid  = threadIdx.x;
    const int lane = tid & 31;
    const int wid  = tid >> 5;

    // ---- preload idx / biases / LN params ----
    if (tid < 256) b1s[tid] = b1[tid];
    b2s[tid]  = b2[tid];
    lngs[tid] = ln_g[tid];
    lnbs[tid] = ln_b[tid];
    {
        int e = tid;
        idx_s[e] = gidx[blockIdx.x * (GB * N1) + e];
        e += THREADS;
        if (e < GB * N1) idx_s[e] = gidx[blockIdx.x * (GB * N1) + e];
    }

    const float* rgb_cta = rgb + (size_t)blockIdx.x * (GB * HN * N1);
    const float* tir_cta = tir + (size_t)blockIdx.x * (GB * HN * N1);

    // ======== scatter + LayerNorm + fp16 hi/lo split, in two 32-row passes ========
    for (int p = 0; p < 2; p++) {
        __syncthreads();
        float4* z = (float4*)x32;
        #pragma unroll
        for (int i = 0; i < (32 * 512 / 4) / THREADS; i++)
            z[tid + i * THREADS] = make_float4(0.f, 0.f, 0.f, 0.f);
        __syncthreads();

        const int ebase = p * (2 * HN * N1);
        #pragma unroll
        for (int ii = 0; ii < (2 * HN * N1) / THREADS; ii++) {
            int e   = ii * THREADS + tid;
            int row = e / N1;                  // 0..31
            int j   = e - row * N1;
            int g   = row >> 4;                // local batch 0/1
            int c   = idx_s[(2 * p + g) * N1 + j];
            x32[row * 512 + c]        = rgb_cta[ebase + e];
            x32[row * 512 + DIM + c]  = tir_cta[ebase + e];
        }
        __syncthreads();

        #pragma unroll
        for (int rr = 0; rr < 2; rr++) {
            int rl = wid * 2 + rr;             // 0..31
            int rg = p * 32 + rl;              // global row
            const float* xr = x32 + rl * 512;
            float s = 0.f, sq = 0.f;
            #pragma unroll
            for (int k = lane; k < 512; k += 32) {
                float v = xr[k]; s += v; sq += v * v;
            }
            #pragma unroll
            for (int o = 16; o > 0; o >>= 1) {
                s  += __shfl_xor_sync(~0u, s,  o);
                sq += __shfl_xor_sync(~0u, sq, o);
            }
            float mu = s * (1.f / 512.f);
            float rs = rsqrtf(sq * (1.f / 512.f) - mu * mu + EPS);
            #pragma unroll
            for (int k2 = lane; k2 < 256; k2 += 32) {
                float2 v  = *(const float2*)(xr + 2 * k2);
                float2 g2 = *(const float2*)(lngs + 2 * k2);
                float2 bb = *(const float2*)(lnbs + 2 * k2);
                float v0 = (v.x - mu) * rs * g2.x + bb.x;
                float v1 = (v.y - mu) * rs * g2.y + bb.y;
                __half2 hi = __floats2half2_rn(v0, v1);
                float2 hf = __half22float2(hi);
                __half2 lo = __floats2half2_rn(v0 - hf.x, v1 - hf.y);
                xhi[rg * XSTRIDE_W + k2] = *(uint32_t*)&hi;
                xlo[rg * XSTRIDE_W + k2] = *(uint32_t*)&lo;
            }
        }
    }
    __syncthreads();

    // ---- warp tile geometry (shared by both GEMMs) ----
    const int mtile  = wid & 3, ngroup = wid >> 2;
    const int m0     = mtile * 16;
    const int q      = lane >> 3, qr = lane & 7;
    const int arow   = m0 + (q & 1) * 8 + qr;
    const uint32_t acol = (q >> 1) * 16;   // bytes
    const uint32_t xhi_a = smem_u32(smem + OFF_XHI) + arow * XSTRIDE_B + acol;
    const uint32_t xlo_a = smem_u32(smem + OFF_XLO) + arow * XSTRIDE_B + acol;

    // ======== GEMM1: [64x512] @ W1hi^T -> h [64x256], 2-product fp16 split ========
    {
        float acc[8][4];
        #pragma unroll
        for (int nt = 0; nt < 8; nt++)
            { acc[nt][0]=0.f; acc[nt][1]=0.f; acc[nt][2]=0.f; acc[nt][3]=0.f; }

        #pragma unroll 2
        for (int kp = 0; kp < 16; kp++) {
            uint32_t ah0[4], ah1[4], al0[4], al1[4];
            ldsm4(ah0, xhi_a + kp * 64);
            ldsm4(ah1, xhi_a + kp * 64 + 32);
            ldsm4(al0, xlo_a + kp * 64);
            ldsm4(al1, xlo_a + kp * 64 + 32);
            #pragma unroll
            for (int nt = 0; nt < 8; nt++) {
                int ntile = ngroup * 8 + nt;
                uint4 bh = __ldg(((const uint4*)g_W1s) + (ntile * 16 + kp) * 32 + lane);
                mma16816(acc[nt], ah0, bh.x, bh.y);
                mma16816(acc[nt], ah1, bh.z, bh.w);
                mma16816(acc[nt], al0, bh.x, bh.y);
                mma16816(acc[nt], al1, bh.z, bh.w);
            }
        }
        // epilogue: +bias, relu, split, store h (overwrites dead x32 region)
        int r0 = m0 + (lane >> 2), r1 = r0 + 8;
        int cwb = ngroup * 32 + (lane & 3);
        #pragma unroll
        for (int nt = 0; nt < 8; nt++) {
            int cw = cwb + nt * 4;
            float2 bb = *(const float2*)(b1s + 2 * cw);
            float v00 = fmaxf(acc[nt][0] + bb.x, 0.f);
            float v01 = fmaxf(acc[nt][1] + bb.y, 0.f);
            float v10 = fmaxf(acc[nt][2] + bb.x, 0.f);
            float v11 = fmaxf(acc[nt][3] + bb.y, 0.f);
            __half2 h0 = __floats2half2_rn(v00, v01);
            float2 h0f = __half22float2(h0);
            __half2 l0 = __floats2half2_rn(v00 - h0f.x, v01 - h0f.y);
            __half2 h1 = __floats2half2_rn(v10, v11);
            float2 h1f = __half22float2(h1);
            __half2 l1 = __floats2half2_rn(v10 - h1f.x, v11 - h1f.y);
            hhi[r0 * HSTRIDE_W + cw] = *(uint32_t*)&h0;
            hlo[r0 * HSTRIDE_W + cw] = *(uint32_t*)&l0;
            hhi[r1 * HSTRIDE_W + cw] = *(uint32_t*)&h1;
            hlo[r1 * HSTRIDE_W + cw] = *(uint32_t*)&l1;
        }
    }
    __syncthreads();

    // ======== GEMM2 (two 256-col halves) + sigmoid + gather ========
    const uint32_t hhi_a = smem_u32(smem + OFF_R1) + arow * HSTRIDE_B + acol;
    const uint32_t hlo_a = hhi_a + 33792;
    const size_t out_base = (size_t)blockIdx.x * (GB * HN * N1);
    const size_t TIR_OFF  = (size_t)BATCH * HN * N1;

    #pragma unroll 1
    for (int hf = 0; hf < 2; hf++) {
        float acc[8][4];
        #pragma unroll
        for (int nt = 0; nt < 8; nt++)
            { acc[nt][0]=0.f; acc[nt][1]=0.f; acc[nt][2]=0.f; acc[nt][3]=0.f; }

        #pragma unroll 2
        for (int kp = 0; kp < 8; kp++) {
            uint32_t ah0[4], ah1[4], al0[4], al1[4];
            ldsm4(ah0, hhi_a + kp * 64);
            ldsm4(ah1, hhi_a + kp * 64 + 32);
            ldsm4(al0, hlo_a + kp * 64);
            ldsm4(al1, hlo_a + kp * 64 + 32);
            #pragma unroll
            for (int nt = 0; nt < 8; nt++) {
                int ntile = hf * 32 + ngroup * 8 + nt;
                uint4 bh = __ldg(((const uint4*)g_W2s) + (ntile * 8 + kp) * 32 + lane);
                mma16816(acc[nt], ah0, bh.x, bh.y);
                mma16816(acc[nt], ah1, bh.z, bh.w);
                mma16816(acc[nt], al0, bh.x, bh.y);
                mma16816(acc[nt], al1, bh.z, bh.w);
            }
        }
        // epilogue: +bias, sigmoid, store to o (overwrites dead xhi region)
        {
            int r0 = m0 + (lane >> 2), r1 = r0 + 8;
            int clb = ngroup * 64 + 2 * (lane & 3);
            #pragma unroll
            for (int nt = 0; nt < 8; nt++) {
                int c = clb + nt * 8;
                float2 bb = *(const float2*)(b2s + hf * 256 + c);
                float2 v0 = make_float2(sigmoidf(acc[nt][0] + bb.x),
                                        sigmoidf(acc[nt][1] + bb.y));
                float2 v1 = make_float2(sigmoidf(acc[nt][2] + bb.x),
                                        sigmoidf(acc[nt][3] + bb.y));
                *(float2*)(osm + r0 * OSTRIDE_W + c) = v0;
                *(float2*)(osm + r1 * OSTRIDE_W + c) = v1;
            }
        }
        __syncthreads();

        // gather this half's outputs
        const size_t obase = (hf ? TIR_OFF : 0) + out_base;
        #pragma unroll
        for (int ii = 0; ii < (GB * HN * N1) / THREADS; ii++) {
            int e   = ii * THREADS + tid;
            int row = e / N1;              // 0..63
            int j   = e - row * N1;
            int g   = row >> 4;
            int c   = idx_s[g * N1 + j];
            out[obase + e] = osm[row * OSTRIDE_W + c];
        }
        __syncthreads();
    }
}

extern "C" void kernel_launch(void* const* d_in, const int* in_sizes, int n_in,
                              void* d_out, int out_size) {
    const float* rgb  = (const float*)d_in[0];
    const float* tir  = (const float*)d_in[1];
    const int*   gidx = (const int*)  d_in[2];
    const float* ln_g = (const float*)d_in[3];
    const float* ln_b = (const float*)d_in[4];
    const float* W1   = (const float*)d_in[5];
    const float* b1   = (const float*)d_in[6];
    const float* W2   = (const float*)d_in[7];
    const float* b2   = (const float*)d_in[8];

    // pre-swizzle weights into fragment order (fp16 hi only)
    prep_weights<<<256, 256>>>(W1, 0, 32, 16, 512);
    prep_weights<<<256, 256>>>(W2, 1, 64, 8, 256);

    cudaFuncSetAttribute(mlp_two_main,
                         cudaFuncAttributeMaxDynamicSharedMemorySize, SMEM_BYTES);
    mlp_two_main<<<BATCH / GB, THREADS, SMEM_BYTES>>>(
        rgb, tir, gidx, ln_g, ln_b, b1, b2, (float*)d_out);
}

// round 10
// speedup vs baseline: 6.7899x; 1.3244x over previous
#include <cuda_runtime.h>
#include <cuda_fp16.h>
#include <cstdint>

#define BATCH   4096
#define HN      16
#define N1      192
#define DIM     256
#define TWO_DIM 512
#define EPS     1e-5f
#define GB      4            // batches per CTA
#define THREADS 512

// ---- smem layout (bytes) ----
#define OFF_R1   0           // x32 staging 32x512 f32 (65536) -> later h fp16 (64x528 = 33792)
#define OFF_XHI  65536       // xhi fp16 64x1040 = 66560 -> later o f32 (64x260x4 = 66560)
#define OFF_IDX  132096      // 768 ints
#define OFF_B1   135168      // 256 f32
#define OFF_B2   136192      // 512 f32
#define OFF_LNG  138240      // 512 f32
#define OFF_LNB  140288      // 512 f32
#define SMEM_BYTES 142336

#define XSTRIDE_W 260        // u32 words per xhi row (256 data + 4 pad; ≡4 mod 32)
#define XSTRIDE_B 1040
#define HSTRIDE_W 132        // u32 words per h row (128 data + 4 pad)
#define HSTRIDE_B 528
#define OSTRIDE_W 260        // f32 words per o row (256 data + 4 pad)

// Pre-swizzled fp16 weights in B-fragment order. 256KB each.
__device__ __align__(16) __half g_W1s[131072];
__device__ __align__(16) __half g_W2s[131072];

__device__ __forceinline__ uint32_t smem_u32(const void* p) {
    return (uint32_t)__cvta_generic_to_shared(p);
}

__device__ __forceinline__ void ldsm4(uint32_t (&r)[4], uint32_t addr) {
    asm volatile("ldmatrix.sync.aligned.m8n8.x4.shared.b16 {%0,%1,%2,%3}, [%4];"
                 : "=r"(r[0]), "=r"(r[1]), "=r"(r[2]), "=r"(r[3]) : "r"(addr));
}

__device__ __forceinline__ void mma16816(float (&c)[4], const uint32_t (&a)[4],
                                         uint32_t b0, uint32_t b1) {
    asm volatile("mma.sync.aligned.m16n8k16.row.col.f32.f16.f16.f32 "
                 "{%0,%1,%2,%3}, {%4,%5,%6,%7}, {%8,%9}, {%0,%1,%2,%3};"
                 : "+f"(c[0]), "+f"(c[1]), "+f"(c[2]), "+f"(c[3])
                 : "r"(a[0]), "r"(a[1]), "r"(a[2]), "r"(a[3]), "r"(b0), "r"(b1));
}

__device__ __forceinline__ float sigmoidf(float x) {
    return 1.0f / (1.0f + __expf(-x));
}

// Swizzle both W1[256][512] and W2[512][256] into per-tile B-fragment order (fp16).
// For each W: u32 index t = ((ntile*kpairs + kp)*32 + lane)*4 + j
__global__ void prep_weights(const float* __restrict__ W1,
                             const float* __restrict__ W2) {
    int t = blockIdx.x * blockDim.x + threadIdx.x;   // [0, 131072)
    const float* W;
    __half2* dst;
    int kpairs, K;
    if (t < 65536) { W = W1; dst = (__half2*)g_W1s; kpairs = 16; K = 512; }
    else           { W = W2; dst = (__half2*)g_W2s; kpairs = 8;  K = 256; t -= 65536; }
    int j    = t & 3;
    int lane = (t >> 2) & 31;
    int rest = t >> 7;
    int kp    = rest % kpairs;
    int ntile = rest / kpairs;
    int n = ntile * 8 + (lane >> 2);
    int k = kp * 32 + (j >> 1) * 16 + (j & 1) * 8 + 2 * (lane & 3);
    dst[(((ntile * kpairs + kp) * 32 + lane) << 2) + j] =
        __floats2half2_rn(W[n * K + k], W[n * K + k + 1]);
}

__global__ __launch_bounds__(THREADS, 1)
void mlp_two_main(const float* __restrict__ rgb, const float* __restrict__ tir,
                  const int* __restrict__ gidx, const float* __restrict__ ln_g,
                  const float* __restrict__ ln_b, const float* __restrict__ b1,
                  const float* __restrict__ b2, float* __restrict__ out)
{
    extern __shared__ char smem[];
    float*    x32  = (float*)(smem + OFF_R1);
    uint32_t* hsm  = (uint32_t*)(smem + OFF_R1);
    uint32_t* xhi  = (uint32_t*)(smem + OFF_XHI);
    float*    osm  = (float*)(smem + OFF_XHI);
    int*      idx_s = (int*)(smem + OFF_IDX);
    float*    b1s  = (float*)(smem + OFF_B1);
    float*    b2s  = (float*)(smem + OFF_B2);
    float*    lngs = (float*)(smem + OFF_LNG);
    float*    lnbs = (float*)(smem + OFF_LNB);

    const int tid  = threadIdx.x;
    const int lane = tid & 31;
    const int wid  = tid >> 5;

    // ---- preload idx / biases / LN params ----
    if (tid < 256) b1s[tid] = b1[tid];
    b2s[tid]  = b2[tid];
    lngs[tid] = ln_g[tid];
    lnbs[tid] = ln_b[tid];
    {
        int e = tid;
        idx_s[e] = gidx[blockIdx.x * (GB * N1) + e];
        e += THREADS;
        if (e < GB * N1) idx_s[e] = gidx[blockIdx.x * (GB * N1) + e];
    }

    const float* rgb_cta = rgb + (size_t)blockIdx.x * (GB * HN * N1);
    const float* tir_cta = tir + (size_t)blockIdx.x * (GB * HN * N1);

    // ======== scatter + LayerNorm + fp16 round, in two 32-row passes ========
    for (int p = 0; p < 2; p++) {
        __syncthreads();
        float4* z = (float4*)x32;
        #pragma unroll
        for (int i = 0; i < (32 * 512 / 4) / THREADS; i++)
            z[tid + i * THREADS] = make_float4(0.f, 0.f, 0.f, 0.f);
        __syncthreads();

        const int ebase = p * (2 * HN * N1);
        #pragma unroll
        for (int ii = 0; ii < (2 * HN * N1) / THREADS; ii++) {
            int e   = ii * THREADS + tid;
            int row = e / N1;                  // 0..31
            int j   = e - row * N1;
            int g   = row >> 4;                // local batch 0/1
            int c   = idx_s[(2 * p + g) * N1 + j];
            x32[row * 512 + c]        = rgb_cta[ebase + e];
            x32[row * 512 + DIM + c]  = tir_cta[ebase + e];
        }
        __syncthreads();

        #pragma unroll
        for (int rr = 0; rr < 2; rr++) {
            int rl = wid * 2 + rr;             // 0..31
            int rg = p * 32 + rl;              // global row
            const float* xr = x32 + rl * 512;
            float s = 0.f, sq = 0.f;
            #pragma unroll
            for (int k = lane; k < 512; k += 32) {
                float v = xr[k]; s += v; sq += v * v;
            }
            #pragma unroll
            for (int o = 16; o > 0; o >>= 1) {
                s  += __shfl_xor_sync(~0u, s,  o);
                sq += __shfl_xor_sync(~0u, sq, o);
            }
            float mu = s * (1.f / 512.f);
            float rs = rsqrtf(sq * (1.f / 512.f) - mu * mu + EPS);
            #pragma unroll
            for (int k2 = lane; k2 < 256; k2 += 32) {
                float2 v  = *(const float2*)(xr + 2 * k2);
                float2 g2 = *(const float2*)(lngs + 2 * k2);
                float2 bb = *(const float2*)(lnbs + 2 * k2);
                float v0 = (v.x - mu) * rs * g2.x + bb.x;
                float v1 = (v.y - mu) * rs * g2.y + bb.y;
                __half2 hi = __floats2half2_rn(v0, v1);
                xhi[rg * XSTRIDE_W + k2] = *(uint32_t*)&hi;
            }
        }
    }
    __syncthreads();

    // ---- warp tile geometry (shared by both GEMMs) ----
    const int mtile  = wid & 3, ngroup = wid >> 2;
    const int m0     = mtile * 16;
    const int q      = lane >> 3, qr = lane & 7;
    const int arow   = m0 + (q & 1) * 8 + qr;
    const uint32_t acol = (q >> 1) * 16;   // bytes
    const uint32_t xhi_a = smem_u32(smem + OFF_XHI) + arow * XSTRIDE_B + acol;

    // ======== GEMM1: [64x512] @ W1^T -> h [64x256], single-pass fp16 ========
    {
        float acc[8][4];
        #pragma unroll
        for (int nt = 0; nt < 8; nt++)
            { acc[nt][0]=0.f; acc[nt][1]=0.f; acc[nt][2]=0.f; acc[nt][3]=0.f; }

        #pragma unroll 4
        for (int kp = 0; kp < 16; kp++) {
            uint32_t ah0[4], ah1[4];
            ldsm4(ah0, xhi_a + kp * 64);
            ldsm4(ah1, xhi_a + kp * 64 + 32);
            #pragma unroll
            for (int nt = 0; nt < 8; nt++) {
                int ntile = ngroup * 8 + nt;
                uint4 bh = __ldg(((const uint4*)g_W1s) + (ntile * 16 + kp) * 32 + lane);
                mma16816(acc[nt], ah0, bh.x, bh.y);
                mma16816(acc[nt], ah1, bh.z, bh.w);
            }
        }
        // epilogue: +bias, relu, fp16 round, store h (overwrites dead x32 region)
        int r0 = m0 + (lane >> 2), r1 = r0 + 8;
        int cwb = ngroup * 32 + (lane & 3);
        #pragma unroll
        for (int nt = 0; nt < 8; nt++) {
            int cw = cwb + nt * 4;
            float2 bb = *(const float2*)(b1s + 2 * cw);
            __half2 h0 = __floats2half2_rn(fmaxf(acc[nt][0] + bb.x, 0.f),
                                           fmaxf(acc[nt][1] + bb.y, 0.f));
            __half2 h1 = __floats2half2_rn(fmaxf(acc[nt][2] + bb.x, 0.f),
                                           fmaxf(acc[nt][3] + bb.y, 0.f));
            hsm[r0 * HSTRIDE_W + cw] = *(uint32_t*)&h0;
            hsm[r1 * HSTRIDE_W + cw] = *(uint32_t*)&h1;
        }
    }
    __syncthreads();

    // ======== GEMM2 (two 256-col halves) + sigmoid + gather ========
    const uint32_t h_a = smem_u32(smem + OFF_R1) + arow * HSTRIDE_B + acol;
    const size_t out_base = (size_t)blockIdx.x * (GB * HN * N1);
    const size_t TIR_OFF  = (size_t)BATCH * HN * N1;

    #pragma unroll 1
    for (int hf = 0; hf < 2; hf++) {
        float acc[8][4];
        #pragma unroll
        for (int nt = 0; nt < 8; nt++)
            { acc[nt][0]=0.f; acc[nt][1]=0.f; acc[nt][2]=0.f; acc[nt][3]=0.f; }

        #pragma unroll 4
        for (int kp = 0; kp < 8; kp++) {
            uint32_t ah0[4], ah1[4];
            ldsm4(ah0, h_a + kp * 64);
            ldsm4(ah1, h_a + kp * 64 + 32);
            #pragma unroll
            for (int nt = 0; nt < 8; nt++) {
                int ntile = hf * 32 + ngroup * 8 + nt;
                uint4 bh = __ldg(((const uint4*)g_W2s) + (ntile * 8 + kp) * 32 + lane);
                mma16816(acc[nt], ah0, bh.x, bh.y);
                mma16816(acc[nt], ah1, bh.z, bh.w);
            }
        }
        // epilogue: +bias, sigmoid, store to o (overwrites dead xhi region)
        {
            int r0 = m0 + (lane >> 2), r1 = r0 + 8;
            int clb = ngroup * 64 + 2 * (lane & 3);
            #pragma unroll
            for (int nt = 0; nt < 8; nt++) {
                int c = clb + nt * 8;
                float2 bb = *(const float2*)(b2s + hf * 256 + c);
                float2 v0 = make_float2(sigmoidf(acc[nt][0] + bb.x),
                                        sigmoidf(acc[nt][1] + bb.y));
                float2 v1 = make_float2(sigmoidf(acc[nt][2] + bb.x),
                                        sigmoidf(acc[nt][3] + bb.y));
                *(float2*)(osm + r0 * OSTRIDE_W + c) = v0;
                *(float2*)(osm + r1 * OSTRIDE_W + c) = v1;
            }
        }
        __syncthreads();

        // gather this half's outputs
        const size_t obase = (hf ? TIR_OFF : 0) + out_base;
        #pragma unroll
        for (int ii = 0; ii < (GB * HN * N1) / THREADS; ii++) {
            int e   = ii * THREADS + tid;
            int row = e / N1;              // 0..63
            int j   = e - row * N1;
            int g   = row >> 4;
            int c   = idx_s[g * N1 + j];
            out[obase + e] = osm[row * OSTRIDE_W + c];
        }
        __syncthreads();
    }
}

extern "C" void kernel_launch(void* const* d_in, const int* in_sizes, int n_in,
                              void* d_out, int out_size) {
    const float* rgb  = (const float*)d_in[0];
    const float* tir  = (const float*)d_in[1];
    const int*   gidx = (const int*)  d_in[2];
    const float* ln_g = (const float*)d_in[3];
    const float* ln_b = (const float*)d_in[4];
    const float* W1   = (const float*)d_in[5];
    const float* b1   = (const float*)d_in[6];
    const float* W2   = (const float*)d_in[7];
    const float* b2   = (const float*)d_in[8];

    // pre-swizzle both weight matrices in a single launch
    prep_weights<<<512, 256>>>(W1, W2);

    cudaFuncSetAttribute(mlp_two_main,
                         cudaFuncAttributeMaxDynamicSharedMemorySize, SMEM_BYTES);
    mlp_two_main<<<BATCH / GB, THREADS, SMEM_BYTES>>>(
        rgb, tir, gidx, ln_g, ln_b, b1, b2, (float*)d_out);
}